// round 15
// baseline (speedup 1.0000x reference)
#include <cuda_runtime.h>
#include <cuda_bf16.h>
#include <stdint.h>
#include <math.h>

// Problem constants
#define NB 4
#define NT 2048
#define NC 1024
#define NH 16
#define ND 64
#define NM (NB * NT)      // 8192
#define NQKV (3 * NC)     // 3072

#define QSCALE (0.125f * 1.44269504088896340736f)   // 1/sqrt(64) * log2(e)

// ---------------------------------------------------------------------------
// Scratch (device globals — no runtime allocation allowed)
// ---------------------------------------------------------------------------
__device__ __nv_bfloat16 g_ah   [(size_t)NM * NC];
__device__ __nv_bfloat16 g_al   [(size_t)NM * NC];
__device__ __nv_bfloat16 g_wqT_h[(size_t)NQKV * NC];   // w_qkv^T  [N][K]
__device__ __nv_bfloat16 g_wqT_l[(size_t)NQKV * NC];
__device__ __nv_bfloat16 g_woT_h[(size_t)NC * NC];     // w_out^T  [N][K]
__device__ __nv_bfloat16 g_woT_l[(size_t)NC * NC];
__device__ __nv_bfloat16 g_atth [(size_t)NM * NC];     // flash out hi [B,T,C]
__device__ __nv_bfloat16 g_attl [(size_t)NM * NC];     // flash out lo

// flash operands, pre-split bf16 (written by QKV epilogue)
__device__ __nv_bfloat16 g_qh [(size_t)NB * NH * NT * ND];  // [bh][t][d] (scaled)
__device__ __nv_bfloat16 g_ql [(size_t)NB * NH * NT * ND];
__device__ __nv_bfloat16 g_kh [(size_t)NB * NH * NT * ND];  // [bh][t][d]
__device__ __nv_bfloat16 g_kl [(size_t)NB * NH * NT * ND];
__device__ __nv_bfloat16 g_vTh[(size_t)NB * NH * ND * NT];  // [bh][d][t]
__device__ __nv_bfloat16 g_vTl[(size_t)NB * NH * ND * NT];

// ---------------------------------------------------------------------------
// PTX helpers (sm_80-class: ldmatrix / mma.sync / cp.async — base sm_103 legal)
// ---------------------------------------------------------------------------
__device__ __forceinline__ uint32_t smem_u32(const void* p) {
    uint32_t a;
    asm("{ .reg .u64 t; cvta.to.shared.u64 t, %1; cvt.u32.u64 %0, t; }"
        : "=r"(a) : "l"(p));
    return a;
}

__device__ __forceinline__ void ldm_x4(uint32_t* r, uint32_t addr) {
    asm volatile("ldmatrix.sync.aligned.m8n8.x4.shared.b16 {%0,%1,%2,%3}, [%4];"
                 : "=r"(r[0]), "=r"(r[1]), "=r"(r[2]), "=r"(r[3]) : "r"(addr));
}

__device__ __forceinline__ void mma_bf16(float* c, const uint32_t* a,
                                         uint32_t b0, uint32_t b1) {
    asm volatile(
        "mma.sync.aligned.m16n8k16.row.col.f32.bf16.bf16.f32 "
        "{%0,%1,%2,%3}, {%4,%5,%6,%7}, {%8,%9}, {%0,%1,%2,%3};"
        : "+f"(c[0]), "+f"(c[1]), "+f"(c[2]), "+f"(c[3])
        : "r"(a[0]), "r"(a[1]), "r"(a[2]), "r"(a[3]), "r"(b0), "r"(b1));
}

#define CP_ASYNC16(dst, src) \
    asm volatile("cp.async.cg.shared.global [%0], [%1], 16;" \
                 :: "r"(dst), "l"(src) : "memory")
#define CP_COMMIT()  asm volatile("cp.async.commit_group;" ::: "memory")
#define CP_WAIT(n)   asm volatile("cp.async.wait_group %0;" :: "n"(n) : "memory")

#define SW128(o) ((o) ^ (((o) >> 3) & 0x70))

// fp32 pair -> bf16x2 hi word + bf16x2 residual word
__device__ __forceinline__ void pack_split(float x, float y,
                                           uint32_t& hi, uint32_t& lo) {
    __nv_bfloat16 hx = __float2bfloat16(x);
    __nv_bfloat16 hy = __float2bfloat16(y);
    __nv_bfloat162 h2(hx, hy);
    hi = *(uint32_t*)&h2;
    __nv_bfloat162 l2(__float2bfloat16(x - __bfloat162float(hx)),
                      __float2bfloat16(y - __bfloat162float(hy)));
    lo = *(uint32_t*)&l2;
}

// ---------------------------------------------------------------------------
// Conversion kernels (fp32 -> bf16 hi/lo split)
// ---------------------------------------------------------------------------
__global__ void convert_split_kernel(const float* __restrict__ in,
                                     __nv_bfloat16* __restrict__ hi,
                                     __nv_bfloat16* __restrict__ lo, int n4)
{
    int i = blockIdx.x * blockDim.x + threadIdx.x;
    if (i >= n4) return;
    float4 v = ((const float4*)in)[i];
    uint32_t h0, l0, h1, l1;
    pack_split(v.x, v.y, h0, l0);
    pack_split(v.z, v.w, h1, l1);
    ((uint32_t*)hi)[2 * i]     = h0;
    ((uint32_t*)hi)[2 * i + 1] = h1;
    ((uint32_t*)lo)[2 * i]     = l0;
    ((uint32_t*)lo)[2 * i + 1] = l1;
}

// W [K][N] fp32  ->  Th/Tl [N][K] bf16 (transpose + split)
__global__ void transpose_split_kernel(const float* __restrict__ W,
                                       __nv_bfloat16* __restrict__ Th,
                                       __nv_bfloat16* __restrict__ Tl,
                                       int Kdim, int Ndim)
{
    __shared__ float tile[32][33];
    const int nx = blockIdx.x * 32 + threadIdx.x;
    const int ky = blockIdx.y * 32;
#pragma unroll
    for (int i = threadIdx.y; i < 32; i += 8)
        tile[i][threadIdx.x] = W[(size_t)(ky + i) * Ndim + nx];
    __syncthreads();
    const int k = ky + threadIdx.x;
#pragma unroll
    for (int i = threadIdx.y; i < 32; i += 8) {
        const int n = blockIdx.x * 32 + i;
        const float v = tile[threadIdx.x][i];
        __nv_bfloat16 h = __float2bfloat16(v);
        Th[(size_t)n * Kdim + k] = h;
        Tl[(size_t)n * Kdim + k] = __float2bfloat16(v - __bfloat162float(h));
    }
}

// ---------------------------------------------------------------------------
// mma.sync bf16-split3 GEMM: C[M,NTOT] = A[M,1024] @ B^T + bias
//   C = Ah*Bh + Ah*Bl + Al*Bh  (fp32 accumulate)
// CTA 128xBN, BK=32, 256 threads (8 warps 4x2, warp tile 32x(BN/2)),
// cp.async 3-stage pipeline (ONE barrier per chunk), 80B padded smem rows,
// 2 CTAs/SM co-resident.
// MODE 0: fp32 out + bias.  MODE 1: QKV scatter -> pre-split flash operands.
// ---------------------------------------------------------------------------
#define A_TILE_B 10240               // 128 rows * 80 B

template <int NTOT, int BN, int MODE>
__global__ __launch_bounds__(256, 2)
void gemm_mma(const __nv_bfloat16* __restrict__ Ahg, const __nv_bfloat16* __restrict__ Alg,
              const __nv_bfloat16* __restrict__ Bhg, const __nv_bfloat16* __restrict__ Blg,
              const float* __restrict__ bias, float* __restrict__ out)
{
    constexpr int NW  = BN / 2;        // warp N
    constexpr int NJ8 = BN / 16;       // n8 blocks per warp
    constexpr int NJ2 = BN / 32;       // ldm_x4 B groups per warp
    constexpr int B_TILE_B = BN * 80;
    constexpr int STAGE = 2 * A_TILE_B + 2 * B_TILE_B;
    constexpr int B_CH  = BN * 4;      // 16B chunks per B tile
    constexpr int CH    = 1024 + 2 * B_CH;

    extern __shared__ char smem[];
    const uint32_t sb = smem_u32(smem);
    const int tid = threadIdx.x;
    const int wid = tid >> 5, lane = tid & 31;
    const int wm = wid & 3, wn = wid >> 2;
    const int bn = blockIdx.x, bm = blockIdx.y;

    float acc[2][NJ8][4];
#pragma unroll
    for (int i = 0; i < 2; i++)
#pragma unroll
        for (int j = 0; j < NJ8; j++)
#pragma unroll
            for (int f = 0; f < 4; f++) acc[i][j][f] = 0.0f;

    auto issue_loads = [&](int kc, int st) {
        const uint32_t stb = sb + st * STAGE;
#pragma unroll
        for (int u = 0; u < CH / 256; u++) {
            const int idx = tid + u * 256;
            if (idx < 1024) {
                const int t = idx >> 9;            // 0=Ah 1=Al
                const int local = idx & 511;
                const int r = local >> 2, c = (local & 3) * 16;
                const __nv_bfloat16* src = (t ? Alg : Ahg)
                    + (size_t)(bm * 128 + r) * NC + kc * 32;
                CP_ASYNC16(stb + t * A_TILE_B + r * 80 + c, (const char*)src + c);
            } else {
                const int bidx = idx - 1024;
                const int t = (bidx >= B_CH) ? 1 : 0;  // 0=Bh 1=Bl
                const int local = bidx - t * B_CH;
                const int r = local >> 2, c = (local & 3) * 16;
                const __nv_bfloat16* src = (t ? Blg : Bhg)
                    + (size_t)(bn * BN + r) * NC + kc * 32;
                CP_ASYNC16(stb + 2 * A_TILE_B + t * B_TILE_B + r * 80 + c,
                           (const char*)src + c);
            }
        }
        CP_COMMIT();
    };

    issue_loads(0, 0);
    issue_loads(1, 1);

    const uint32_t lrow = lane & 15;
    const uint32_t lcol = (lane >> 4) * 16;

    for (int kc = 0; kc < 32; kc++) {
        const int st = kc % 3;
        if (kc < 31) CP_WAIT(1); else CP_WAIT(0);
        __syncthreads();                 // data ready + stage (kc+2)%3 free
        if (kc + 2 < 32) issue_loads(kc + 2, (kc + 2) % 3);

        const uint32_t stb = sb + st * STAGE;
#pragma unroll
        for (int k16 = 0; k16 < 2; k16++) {
            const uint32_t koff = k16 * 32 + lcol;
            uint32_t aH[2][4], aL[2][4];
#pragma unroll
            for (int i = 0; i < 2; i++) {
                const uint32_t row = wm * 32 + i * 16 + lrow;
                ldm_x4(aH[i], stb + row * 80 + koff);
                ldm_x4(aL[i], stb + A_TILE_B + row * 80 + koff);
            }
#pragma unroll
            for (int j2 = 0; j2 < NJ2; j2++) {
                const uint32_t row = wn * NW + j2 * 16 + lrow;
                uint32_t bH[4], bL[4];
                ldm_x4(bH, stb + 2 * A_TILE_B + row * 80 + koff);
                ldm_x4(bL, stb + 2 * A_TILE_B + B_TILE_B + row * 80 + koff);
#pragma unroll
                for (int i = 0; i < 2; i++)
#pragma unroll
                    for (int od = 0; od < 2; od++) {
                        const int j = j2 * 2 + od;
                        mma_bf16(acc[i][j], aH[i], bH[od], bH[od + 2]);
                        mma_bf16(acc[i][j], aH[i], bL[od], bL[od + 2]);
                        mma_bf16(acc[i][j], aL[i], bH[od], bH[od + 2]);
                    }
            }
        }
    }

    // Epilogue
    const int rr = lane >> 2;
    const int cc = (lane & 3) * 2;
#pragma unroll
    for (int i = 0; i < 2; i++) {
#pragma unroll
        for (int j = 0; j < NJ8; j++) {
            const int gc = bn * BN + wn * NW + j * 8 + cc;
            const float bz0 = bias[gc], bz1 = bias[gc + 1];
#pragma unroll
            for (int h2 = 0; h2 < 2; h2++) {
                const int gm = bm * 128 + wm * 32 + i * 16 + h2 * 8 + rr;
                const float v0 = acc[i][j][h2 * 2 + 0] + bz0;
                const float v1 = acc[i][j][h2 * 2 + 1] + bz1;
                if (MODE == 0) {
                    *(float2*)&out[(size_t)gm * NTOT + gc] = make_float2(v0, v1);
                } else {
                    const int part = gc >> 10;          // 0=q 1=k 2=v
                    const int h  = (gc & (NC - 1)) >> 6;
                    const int d0 = gc & 63;
                    const int b  = gm >> 11;
                    const int tt = gm & (NT - 1);
                    const int bh = b * NH + h;
                    if (part == 0) {
                        uint32_t hi, lo;
                        pack_split(v0 * QSCALE, v1 * QSCALE, hi, lo);
                        const size_t base = ((size_t)bh * NT + tt) * ND + d0;
                        *(uint32_t*)&g_qh[base] = hi;
                        *(uint32_t*)&g_ql[base] = lo;
                    } else if (part == 1) {
                        uint32_t hi, lo;
                        pack_split(v0, v1, hi, lo);
                        const size_t base = ((size_t)bh * NT + tt) * ND + d0;
                        *(uint32_t*)&g_kh[base] = hi;
                        *(uint32_t*)&g_kl[base] = lo;
                    } else {
                        const size_t base = ((size_t)bh * ND + d0) * NT + tt;
                        __nv_bfloat16 h0 = __float2bfloat16(v0);
                        __nv_bfloat16 h1 = __float2bfloat16(v1);
                        g_vTh[base]      = h0;
                        g_vTh[base + NT] = h1;
                        g_vTl[base]      = __float2bfloat16(v0 - __bfloat162float(h0));
                        g_vTl[base + NT] = __float2bfloat16(v1 - __bfloat162float(h1));
                    }
                }
            }
        }
    }
}

#define GEMM_SMEM_QKV (3 * (2 * A_TILE_B + 2 * 96 * 80))   // 107520
#define GEMM_SMEM_OUT (3 * (2 * A_TILE_B + 2 * 64 * 80))   // 92160

// ---------------------------------------------------------------------------
// Flash attention v2 (tensor-core, bf16 split-3 for S and PV, fp32 softmax)
// CTA: 128 q-rows x one bh. 256 threads = 8 warps, warp = 16 q-rows.
// K-tiles of 64 keys, double-buffered cp.async, 2 CTAs/SM.
// qt reversed (heavy diagonal blocks first) to shorten the tail wave.
// ---------------------------------------------------------------------------
#define FL2_SMEM (32768 + 2 * 32768)   // 98304 B

__global__ __launch_bounds__(256, 2)
void flash2_kernel()
{
    extern __shared__ char smc[];
    const uint32_t sb = smem_u32(smc);
    const int tid = threadIdx.x;
    const int w = tid >> 5, lane = tid & 31;
    const int qt = (gridDim.x - 1) - blockIdx.x;   // heavy blocks first
    const int bh = blockIdx.y;
    const int q0 = qt * 128;

    const __nv_bfloat16* Qh_g = g_qh + ((size_t)bh * NT + q0) * ND;
    const __nv_bfloat16* Ql_g = g_ql + ((size_t)bh * NT + q0) * ND;
    const __nv_bfloat16* Kh_g = g_kh + (size_t)bh * NT * ND;
    const __nv_bfloat16* Kl_g = g_kl + (size_t)bh * NT * ND;
    const __nv_bfloat16* Vh_g = g_vTh + (size_t)bh * ND * NT;
    const __nv_bfloat16* Vl_g = g_vTl + (size_t)bh * ND * NT;

    const uint32_t sQh = sb, sQl = sb + 16384;

    auto load_kv = [&](int jt, int st) {
        const int k0 = jt * 64;
        const uint32_t base = sb + 32768 + st * 32768;
#pragma unroll
        for (int u = 0; u < 2; u++) {
            const int idx = tid + u * 256;            // 0..511
            const int r = idx >> 3, c = (idx & 7) * 16;
            const uint32_t sw = SW128(r * 128 + c);
            CP_ASYNC16(base +         sw, (const char*)(Kh_g + (size_t)(k0 + r) * ND) + c);
            CP_ASYNC16(base +  8192 + sw, (const char*)(Kl_g + (size_t)(k0 + r) * ND) + c);
            CP_ASYNC16(base + 16384 + sw, (const char*)(Vh_g + (size_t)r * NT + k0) + c);
            CP_ASYNC16(base + 24576 + sw, (const char*)(Vl_g + (size_t)r * NT + k0) + c);
        }
        CP_COMMIT();
    };

    // Q tile load (with group 0)
#pragma unroll
    for (int u = 0; u < 4; u++) {
        const int idx = tid + u * 256;                // 0..1023
        const int r = idx >> 3, c = (idx & 7) * 16;
        const uint32_t sw = SW128(r * 128 + c);
        CP_ASYNC16(sQh + sw, (const char*)(Qh_g + (size_t)r * ND) + c);
        CP_ASYNC16(sQl + sw, (const char*)(Ql_g + (size_t)r * ND) + c);
    }
    load_kv(0, 0);
    load_kv(1, 1);

    const int nkt = 2 * qt + 2;
    const uint32_t lrow = lane & 15, lcolB = (lane >> 4) * 16;

    uint32_t qfh[4][4], qfl[4][4];
    float m0 = -1e30f, m1 = -1e30f, l0 = 0.0f, l1 = 0.0f;
    float o[8][4];
#pragma unroll
    for (int j = 0; j < 8; j++)
#pragma unroll
        for (int f = 0; f < 4; f++) o[j][f] = 0.0f;

    for (int jt = 0; jt < nkt; jt++) {
        const int st = jt & 1;
        if (jt + 1 < nkt) CP_WAIT(1); else CP_WAIT(0);
        __syncthreads();

        if (jt == 0) {
#pragma unroll
            for (int kt = 0; kt < 4; kt++) {
                const uint32_t off = SW128((w * 16 + lrow) * 128 + kt * 32 + lcolB);
                ldm_x4(qfh[kt], sQh + off);
                ldm_x4(qfl[kt], sQl + off);
            }
        }

        const bool diag0 = (jt == 2 * qt);
        const bool diag1 = (jt == 2 * qt + 1);
        const bool skip  = diag1 && (w < 4);    // fully masked sub-tile

        if (!skip) {
            const uint32_t kb = sb + 32768 + st * 32768;

            // S = Q K^T (split-3)
            float s[8][4];
#pragma unroll
            for (int j = 0; j < 8; j++)
#pragma unroll
                for (int f = 0; f < 4; f++) s[j][f] = 0.0f;

#pragma unroll
            for (int kt = 0; kt < 4; kt++) {
#pragma unroll
                for (int j2 = 0; j2 < 4; j2++) {
                    const uint32_t off = SW128((j2 * 16 + lrow) * 128 + kt * 32 + lcolB);
                    uint32_t bKh[4], bKl[4];
                    ldm_x4(bKh, kb + off);
                    ldm_x4(bKl, kb + 8192 + off);
#pragma unroll
                    for (int od = 0; od < 2; od++) {
                        const int j = j2 * 2 + od;
                        mma_bf16(s[j], qfh[kt], bKh[od], bKh[od + 2]);
                        mma_bf16(s[j], qfh[kt], bKl[od], bKl[od + 2]);
                        mma_bf16(s[j], qfl[kt], bKh[od], bKh[od + 2]);
                    }
                }
            }

            // causal mask on diagonal sub-tiles
            if ((diag0 && w < 4) || diag1) {
                const int qloc  = w * 16 + (lane >> 2);
                const int kbase = diag1 ? 64 : 0;
#pragma unroll
                for (int j = 0; j < 8; j++) {
                    const int kc = kbase + j * 8 + (lane & 3) * 2;
                    if (kc     > qloc)     s[j][0] = -1e30f;
                    if (kc + 1 > qloc)     s[j][1] = -1e30f;
                    if (kc     > qloc + 8) s[j][2] = -1e30f;
                    if (kc + 1 > qloc + 8) s[j][3] = -1e30f;
                }
            }

            // online softmax (exp2 domain; rows r=lane>>2 and r+8)
            float mx0 = -1e30f, mx1 = -1e30f;
#pragma unroll
            for (int j = 0; j < 8; j++) {
                mx0 = fmaxf(mx0, fmaxf(s[j][0], s[j][1]));
                mx1 = fmaxf(mx1, fmaxf(s[j][2], s[j][3]));
            }
            mx0 = fmaxf(mx0, __shfl_xor_sync(0xffffffffu, mx0, 1));
            mx0 = fmaxf(mx0, __shfl_xor_sync(0xffffffffu, mx0, 2));
            mx1 = fmaxf(mx1, __shfl_xor_sync(0xffffffffu, mx1, 1));
            mx1 = fmaxf(mx1, __shfl_xor_sync(0xffffffffu, mx1, 2));
            const float mn0 = fmaxf(m0, mx0), mn1 = fmaxf(m1, mx1);
            const float f0 = exp2f(m0 - mn0), f1 = exp2f(m1 - mn1);
            float rs0 = 0.0f, rs1 = 0.0f;
#pragma unroll
            for (int j = 0; j < 8; j++) {
                s[j][0] = exp2f(s[j][0] - mn0);
                s[j][1] = exp2f(s[j][1] - mn0);
                s[j][2] = exp2f(s[j][2] - mn1);
                s[j][3] = exp2f(s[j][3] - mn1);
                rs0 += s[j][0] + s[j][1];
                rs1 += s[j][2] + s[j][3];
            }
            rs0 += __shfl_xor_sync(0xffffffffu, rs0, 1);
            rs0 += __shfl_xor_sync(0xffffffffu, rs0, 2);
            rs1 += __shfl_xor_sync(0xffffffffu, rs1, 1);
            rs1 += __shfl_xor_sync(0xffffffffu, rs1, 2);
            l0 = l0 * f0 + rs0; m0 = mn0;
            l1 = l1 * f1 + rs1; m1 = mn1;
#pragma unroll
            for (int j = 0; j < 8; j++) {
                o[j][0] *= f0; o[j][1] *= f0;
                o[j][2] *= f1; o[j][3] *= f1;
            }

            // repack P (C-frag -> A-frag), split hi/lo
            uint32_t ph[4][4], pl[4][4];
#pragma unroll
            for (int kt = 0; kt < 4; kt++) {
                pack_split(s[2 * kt][0],     s[2 * kt][1],     ph[kt][0], pl[kt][0]);
                pack_split(s[2 * kt][2],     s[2 * kt][3],     ph[kt][1], pl[kt][1]);
                pack_split(s[2 * kt + 1][0], s[2 * kt + 1][1], ph[kt][2], pl[kt][2]);
                pack_split(s[2 * kt + 1][2], s[2 * kt + 1][3], ph[kt][3], pl[kt][3]);
            }

            // O += P V (split-3), B = V^T smem [d][key]
            const uint32_t vb = kb + 16384;
#pragma unroll
            for (int kt = 0; kt < 4; kt++) {
#pragma unroll
                for (int j2 = 0; j2 < 4; j2++) {
                    const uint32_t off = SW128((j2 * 16 + lrow) * 128 + kt * 32 + lcolB);
                    uint32_t bVh[4], bVl[4];
                    ldm_x4(bVh, vb + off);
                    ldm_x4(bVl, vb + 8192 + off);
#pragma unroll
                    for (int od = 0; od < 2; od++) {
                        const int j = j2 * 2 + od;
                        mma_bf16(o[j], ph[kt], bVh[od], bVh[od + 2]);
                        mma_bf16(o[j], ph[kt], bVl[od], bVl[od + 2]);
                        mma_bf16(o[j], pl[kt], bVh[od], bVh[od + 2]);
                    }
                }
            }
        }

        __syncthreads();
        if (jt + 2 < nkt) load_kv(jt + 2, st);
    }

    // Epilogue: normalize, split, write g_atth/g_attl [B,T,C]
    const int b = bh >> 4, h = bh & 15;
    const int r0g = q0 + w * 16 + (lane >> 2);
    const float inv0 = 1.0f / l0, inv1 = 1.0f / l1;
#pragma unroll
    for (int j = 0; j < 8; j++) {
        const int dc = j * 8 + (lane & 3) * 2;
        const size_t base = ((size_t)(b * NT + r0g)) * NC + h * 64 + dc;
        uint32_t hi, lo;
        pack_split(o[j][0] * inv0, o[j][1] * inv0, hi, lo);
        *(uint32_t*)&g_atth[base] = hi;
        *(uint32_t*)&g_attl[base] = lo;
        pack_split(o[j][2] * inv1, o[j][3] * inv1, hi, lo);
        *(uint32_t*)&g_atth[base + 8 * NC] = hi;
        *(uint32_t*)&g_attl[base + 8 * NC] = lo;
    }
}

// ---------------------------------------------------------------------------
// kernel_launch
// ---------------------------------------------------------------------------
extern "C" void kernel_launch(void* const* d_in, const int* in_sizes, int n_in,
                              void* d_out, int out_size)
{
    const float* x     = (const float*)d_in[0];
    const float* w_qkv = (const float*)d_in[1];
    const float* b_qkv = (const float*)d_in[2];
    const float* w_out = (const float*)d_in[3];
    const float* b_out = (const float*)d_in[4];
    float* out = (float*)d_out;

    cudaFuncSetAttribute((const void*)flash2_kernel,
                         cudaFuncAttributeMaxDynamicSharedMemorySize, FL2_SMEM);
    cudaFuncSetAttribute((const void*)gemm_mma<NQKV, 96, 1>,
                         cudaFuncAttributeMaxDynamicSharedMemorySize, GEMM_SMEM_QKV);
    cudaFuncSetAttribute((const void*)gemm_mma<NC, 64, 0>,
                         cudaFuncAttributeMaxDynamicSharedMemorySize, GEMM_SMEM_OUT);

    void *p_ah, *p_al, *p_wqh, *p_wql, *p_woh, *p_wol, *p_atth, *p_attl;
    cudaGetSymbolAddress(&p_ah,   g_ah);
    cudaGetSymbolAddress(&p_al,   g_al);
    cudaGetSymbolAddress(&p_wqh,  g_wqT_h);
    cudaGetSymbolAddress(&p_wql,  g_wqT_l);
    cudaGetSymbolAddress(&p_woh,  g_woT_h);
    cudaGetSymbolAddress(&p_wol,  g_woT_l);
    cudaGetSymbolAddress(&p_atth, g_atth);
    cudaGetSymbolAddress(&p_attl, g_attl);

    const int n4 = NM * NC / 4;

    // 1) Split x, transpose+split weights
    convert_split_kernel<<<(n4 + 255) / 256, 256>>>(
        x, (__nv_bfloat16*)p_ah, (__nv_bfloat16*)p_al, n4);
    transpose_split_kernel<<<dim3(NQKV / 32, NC / 32), dim3(32, 8)>>>(
        w_qkv, (__nv_bfloat16*)p_wqh, (__nv_bfloat16*)p_wql, NC, NQKV);
    transpose_split_kernel<<<dim3(NC / 32, NC / 32), dim3(32, 8)>>>(
        w_out, (__nv_bfloat16*)p_woh, (__nv_bfloat16*)p_wol, NC, NC);

    // 2) QKV projection (128x96 tiles) -> pre-split bf16 flash operands
    gemm_mma<NQKV, 96, 1><<<dim3(NQKV / 96, NM / 128), 256, GEMM_SMEM_QKV>>>(
        (const __nv_bfloat16*)p_ah, (const __nv_bfloat16*)p_al,
        (const __nv_bfloat16*)p_wqh, (const __nv_bfloat16*)p_wql,
        b_qkv, nullptr);

    // 3) Tensor-core causal flash attention -> g_atth/g_attl
    flash2_kernel<<<dim3(NT / 128, NB * NH), 256, FL2_SMEM>>>();

    // 4) Output projection (128x64 tiles)
    gemm_mma<NC, 64, 0><<<dim3(NC / 64, NM / 128), 256, GEMM_SMEM_OUT>>>(
        (const __nv_bfloat16*)p_atth, (const __nv_bfloat16*)p_attl,
        (const __nv_bfloat16*)p_woh, (const __nv_bfloat16*)p_wol,
        b_out, out);
}

// round 16
// speedup vs baseline: 1.0347x; 1.0347x over previous
#include <cuda_runtime.h>
#include <cuda_bf16.h>
#include <stdint.h>
#include <math.h>

// Problem constants
#define NB 4
#define NT 2048
#define NC 1024
#define NH 16
#define ND 64
#define NM (NB * NT)      // 8192
#define NQKV (3 * NC)     // 3072

#define QSCALE (0.125f * 1.44269504088896340736f)   // 1/sqrt(64) * log2(e)

// ---------------------------------------------------------------------------
// Scratch (device globals — no runtime allocation allowed)
// ---------------------------------------------------------------------------
__device__ __nv_bfloat16 g_ah   [(size_t)NM * NC];
__device__ __nv_bfloat16 g_al   [(size_t)NM * NC];
__device__ __nv_bfloat16 g_wqT_h[(size_t)NQKV * NC];   // w_qkv^T  [N][K]
__device__ __nv_bfloat16 g_wqT_l[(size_t)NQKV * NC];
__device__ __nv_bfloat16 g_woT_h[(size_t)NC * NC];     // w_out^T  [N][K]
__device__ __nv_bfloat16 g_woT_l[(size_t)NC * NC];
__device__ __nv_bfloat16 g_atth [(size_t)NM * NC];     // flash out hi [B,T,C]
__device__ __nv_bfloat16 g_attl [(size_t)NM * NC];     // flash out lo

// flash operands, pre-split bf16 (written by QKV epilogue)
__device__ __nv_bfloat16 g_qh [(size_t)NB * NH * NT * ND];  // [bh][t][d] (scaled)
__device__ __nv_bfloat16 g_ql [(size_t)NB * NH * NT * ND];
__device__ __nv_bfloat16 g_kh [(size_t)NB * NH * NT * ND];  // [bh][t][d]
__device__ __nv_bfloat16 g_kl [(size_t)NB * NH * NT * ND];
__device__ __nv_bfloat16 g_vTh[(size_t)NB * NH * ND * NT];  // [bh][d][t]
__device__ __nv_bfloat16 g_vTl[(size_t)NB * NH * ND * NT];

// ---------------------------------------------------------------------------
// PTX helpers (sm_80-class: ldmatrix / mma.sync / cp.async — base sm_103 legal)
// ---------------------------------------------------------------------------
__device__ __forceinline__ uint32_t smem_u32(const void* p) {
    uint32_t a;
    asm("{ .reg .u64 t; cvta.to.shared.u64 t, %1; cvt.u32.u64 %0, t; }"
        : "=r"(a) : "l"(p));
    return a;
}

__device__ __forceinline__ void ldm_x4(uint32_t* r, uint32_t addr) {
    asm volatile("ldmatrix.sync.aligned.m8n8.x4.shared.b16 {%0,%1,%2,%3}, [%4];"
                 : "=r"(r[0]), "=r"(r[1]), "=r"(r[2]), "=r"(r[3]) : "r"(addr));
}

__device__ __forceinline__ void mma_bf16(float* c, const uint32_t* a,
                                         uint32_t b0, uint32_t b1) {
    asm volatile(
        "mma.sync.aligned.m16n8k16.row.col.f32.bf16.bf16.f32 "
        "{%0,%1,%2,%3}, {%4,%5,%6,%7}, {%8,%9}, {%0,%1,%2,%3};"
        : "+f"(c[0]), "+f"(c[1]), "+f"(c[2]), "+f"(c[3])
        : "r"(a[0]), "r"(a[1]), "r"(a[2]), "r"(a[3]), "r"(b0), "r"(b1));
}

#define CP_ASYNC16(dst, src) \
    asm volatile("cp.async.cg.shared.global [%0], [%1], 16;" \
                 :: "r"(dst), "l"(src) : "memory")
#define CP_COMMIT()  asm volatile("cp.async.commit_group;" ::: "memory")
#define CP_WAIT(n)   asm volatile("cp.async.wait_group %0;" :: "n"(n) : "memory")

#define SW128(o) ((o) ^ (((o) >> 3) & 0x70))

// fp32 pair -> bf16x2 hi word + bf16x2 residual word
__device__ __forceinline__ void pack_split(float x, float y,
                                           uint32_t& hi, uint32_t& lo) {
    __nv_bfloat16 hx = __float2bfloat16(x);
    __nv_bfloat16 hy = __float2bfloat16(y);
    __nv_bfloat162 h2(hx, hy);
    hi = *(uint32_t*)&h2;
    __nv_bfloat162 l2(__float2bfloat16(x - __bfloat162float(hx)),
                      __float2bfloat16(y - __bfloat162float(hy)));
    lo = *(uint32_t*)&l2;
}

// ---------------------------------------------------------------------------
// Conversion kernels (fp32 -> bf16 hi/lo split)
// ---------------------------------------------------------------------------
__global__ void convert_split_kernel(const float* __restrict__ in,
                                     __nv_bfloat16* __restrict__ hi,
                                     __nv_bfloat16* __restrict__ lo, int n4)
{
    int i = blockIdx.x * blockDim.x + threadIdx.x;
    if (i >= n4) return;
    float4 v = ((const float4*)in)[i];
    uint32_t h0, l0, h1, l1;
    pack_split(v.x, v.y, h0, l0);
    pack_split(v.z, v.w, h1, l1);
    ((uint32_t*)hi)[2 * i]     = h0;
    ((uint32_t*)hi)[2 * i + 1] = h1;
    ((uint32_t*)lo)[2 * i]     = l0;
    ((uint32_t*)lo)[2 * i + 1] = l1;
}

// W [K][N] fp32  ->  Th/Tl [N][K] bf16 (transpose + split)
__global__ void transpose_split_kernel(const float* __restrict__ W,
                                       __nv_bfloat16* __restrict__ Th,
                                       __nv_bfloat16* __restrict__ Tl,
                                       int Kdim, int Ndim)
{
    __shared__ float tile[32][33];
    const int nx = blockIdx.x * 32 + threadIdx.x;
    const int ky = blockIdx.y * 32;
#pragma unroll
    for (int i = threadIdx.y; i < 32; i += 8)
        tile[i][threadIdx.x] = W[(size_t)(ky + i) * Ndim + nx];
    __syncthreads();
    const int k = ky + threadIdx.x;
#pragma unroll
    for (int i = threadIdx.y; i < 32; i += 8) {
        const int n = blockIdx.x * 32 + i;
        const float v = tile[threadIdx.x][i];
        __nv_bfloat16 h = __float2bfloat16(v);
        Th[(size_t)n * Kdim + k] = h;
        Tl[(size_t)n * Kdim + k] = __float2bfloat16(v - __bfloat162float(h));
    }
}

// ---------------------------------------------------------------------------
// mma.sync bf16-split3 GEMM: C[M,NTOT] = A[M,1024] @ B^T + bias
//   C = Ah*Bh + Ah*Bl + Al*Bh  (fp32 accumulate)
// CTA 128x128, BK=32, 256 threads (8 warps 4x2, warp tile 32x64),
// cp.async 2-stage pipeline, 80B padded smem rows, 2 CTAs/SM co-resident.
// Loads use RUNNING GLOBAL POINTERS (+64B/chunk) + static smem destinations
// (kc unrolled by 2) to cut scalar address arithmetic out of the hot loop.
// MODE 0: fp32 out + bias.  MODE 1: QKV scatter -> pre-split flash operands.
// ---------------------------------------------------------------------------
#define TILE_B   10240               // 128 rows * 80 B
#define STAGE_B  (4 * TILE_B)        // Ah, Al, Bh, Bl
#define GEMM_SMEM (2 * STAGE_B)      // 81920 B (2 stages -> 2 CTAs/SM)

template <int NTOT, int MODE>
__global__ __launch_bounds__(256, 2)
void gemm_mma(const __nv_bfloat16* __restrict__ Ahg, const __nv_bfloat16* __restrict__ Alg,
              const __nv_bfloat16* __restrict__ Bhg, const __nv_bfloat16* __restrict__ Blg,
              const float* __restrict__ bias, float* __restrict__ out)
{
    extern __shared__ char smem[];
    const uint32_t sb = smem_u32(smem);
    const int tid = threadIdx.x;
    const int wid = tid >> 5, lane = tid & 31;
    const int wm = wid & 3, wn = wid >> 2;
    const int bn = blockIdx.x, bm = blockIdx.y;

    float acc[2][8][4];
#pragma unroll
    for (int i = 0; i < 2; i++)
#pragma unroll
        for (int j = 0; j < 8; j++)
#pragma unroll
            for (int f = 0; f < 4; f++) acc[i][j][f] = 0.0f;

    // Running global pointers: thread owns rows r0 and r0+64 of each tile,
    // fixed byte column; advances +64 B per chunk.
    const int r0 = tid >> 2;
    const int cB = (tid & 3) * 16;
    const char* pld[4];
    pld[0] = (const char*)(Ahg + (size_t)(bm * 128 + r0) * NC) + cB;
    pld[1] = (const char*)(Alg + (size_t)(bm * 128 + r0) * NC) + cB;
    pld[2] = (const char*)(Bhg + (size_t)(bn * 128 + r0) * NC) + cB;
    pld[3] = (const char*)(Blg + (size_t)(bn * 128 + r0) * NC) + cB;
    const size_t rowOfs = (size_t)64 * NC * 2;       // +64 rows, bytes
    const uint32_t dst0 = sb + (uint32_t)(r0 * 80 + cB);

    auto issue_st = [&](uint32_t stage_off) {
#pragma unroll
        for (int t = 0; t < 4; t++) {
            const uint32_t d = dst0 + stage_off + t * TILE_B;
            CP_ASYNC16(d,           pld[t]);
            CP_ASYNC16(d + 64 * 80, pld[t] + rowOfs);
        }
        CP_COMMIT();
#pragma unroll
        for (int t = 0; t < 4; t++) pld[t] += 64;     // next 32 bf16 columns
    };

    const uint32_t lrow = lane & 15;
    const uint32_t lcol = (lane >> 4) * 16;

    auto compute_st = [&](uint32_t stage_off) {
        const uint32_t stb = sb + stage_off;
#pragma unroll
        for (int k16 = 0; k16 < 2; k16++) {
            const uint32_t koff = k16 * 32 + lcol;
            uint32_t aH[2][4], aL[2][4], bH[4][4], bL[4][4];
#pragma unroll
            for (int i = 0; i < 2; i++) {
                const uint32_t row = wm * 32 + i * 16 + lrow;
                ldm_x4(aH[i], stb + row * 80 + koff);
                ldm_x4(aL[i], stb + TILE_B + row * 80 + koff);
            }
#pragma unroll
            for (int j2 = 0; j2 < 4; j2++) {
                const uint32_t row = wn * 64 + j2 * 16 + lrow;
                ldm_x4(bH[j2], stb + 2 * TILE_B + row * 80 + koff);
                ldm_x4(bL[j2], stb + 3 * TILE_B + row * 80 + koff);
            }
#pragma unroll
            for (int i = 0; i < 2; i++)
#pragma unroll
                for (int j = 0; j < 8; j++) {
                    const int j2 = j >> 1, o = j & 1;
                    mma_bf16(acc[i][j], aH[i], bH[j2][o], bH[j2][o + 2]);
                    mma_bf16(acc[i][j], aH[i], bL[j2][o], bL[j2][o + 2]);
                    mma_bf16(acc[i][j], aL[i], bH[j2][o], bH[j2][o + 2]);
                }
        }
    };

    issue_st(0);                       // chunk 0 -> stage 0

#pragma unroll 1
    for (int kc2 = 0; kc2 < 16; kc2++) {
        // chunk 2*kc2 (stage 0)
        __syncthreads();
        issue_st(STAGE_B);             // chunk 2*kc2+1 -> stage 1 (always valid)
        CP_WAIT(1);
        __syncthreads();
        compute_st(0);

        // chunk 2*kc2+1 (stage 1)
        __syncthreads();
        if (kc2 < 15) {
            issue_st(0);               // chunk 2*kc2+2 -> stage 0
            CP_WAIT(1);
        } else {
            CP_WAIT(0);
        }
        __syncthreads();
        compute_st(STAGE_B);
    }

    // Epilogue
    const int rr = lane >> 2;
    const int cc = (lane & 3) * 2;
#pragma unroll
    for (int i = 0; i < 2; i++) {
#pragma unroll
        for (int j = 0; j < 8; j++) {
            const int gc = bn * 128 + wn * 64 + j * 8 + cc;
            const float bz0 = bias[gc], bz1 = bias[gc + 1];
#pragma unroll
            for (int h2 = 0; h2 < 2; h2++) {
                const int gm = bm * 128 + wm * 32 + i * 16 + h2 * 8 + rr;
                const float v0 = acc[i][j][h2 * 2 + 0] + bz0;
                const float v1 = acc[i][j][h2 * 2 + 1] + bz1;
                if (MODE == 0) {
                    *(float2*)&out[(size_t)gm * NTOT + gc] = make_float2(v0, v1);
                } else {
                    const int part = gc >> 10;          // 0=q 1=k 2=v
                    const int h  = (gc & (NC - 1)) >> 6;
                    const int d0 = gc & 63;
                    const int b  = gm >> 11;
                    const int tt = gm & (NT - 1);
                    const int bh = b * NH + h;
                    if (part == 0) {
                        uint32_t hi, lo;
                        pack_split(v0 * QSCALE, v1 * QSCALE, hi, lo);
                        const size_t base = ((size_t)bh * NT + tt) * ND + d0;
                        *(uint32_t*)&g_qh[base] = hi;
                        *(uint32_t*)&g_ql[base] = lo;
                    } else if (part == 1) {
                        uint32_t hi, lo;
                        pack_split(v0, v1, hi, lo);
                        const size_t base = ((size_t)bh * NT + tt) * ND + d0;
                        *(uint32_t*)&g_kh[base] = hi;
                        *(uint32_t*)&g_kl[base] = lo;
                    } else {
                        const size_t base = ((size_t)bh * ND + d0) * NT + tt;
                        __nv_bfloat16 h0 = __float2bfloat16(v0);
                        __nv_bfloat16 h1 = __float2bfloat16(v1);
                        g_vTh[base]      = h0;
                        g_vTh[base + NT] = h1;
                        g_vTl[base]      = __float2bfloat16(v0 - __bfloat162float(h0));
                        g_vTl[base + NT] = __float2bfloat16(v1 - __bfloat162float(h1));
                    }
                }
            }
        }
    }
}

// ---------------------------------------------------------------------------
// Flash attention v2 (tensor-core, bf16 split-3 for S and PV, fp32 softmax)
// CTA: 128 q-rows x one bh. 256 threads = 8 warps, warp = 16 q-rows.
// K-tiles of 64 keys, double-buffered cp.async.  (exact R11 configuration)
// ---------------------------------------------------------------------------
#define FL2_SMEM (32768 + 2 * 32768)   // 98304 B

__global__ __launch_bounds__(256, 1)
void flash2_kernel()
{
    extern __shared__ char smc[];
    const uint32_t sb = smem_u32(smc);
    const int tid = threadIdx.x;
    const int w = tid >> 5, lane = tid & 31;
    const int qt = blockIdx.x, bh = blockIdx.y;
    const int q0 = qt * 128;

    const __nv_bfloat16* Qh_g = g_qh + ((size_t)bh * NT + q0) * ND;
    const __nv_bfloat16* Ql_g = g_ql + ((size_t)bh * NT + q0) * ND;
    const __nv_bfloat16* Kh_g = g_kh + (size_t)bh * NT * ND;
    const __nv_bfloat16* Kl_g = g_kl + (size_t)bh * NT * ND;
    const __nv_bfloat16* Vh_g = g_vTh + (size_t)bh * ND * NT;
    const __nv_bfloat16* Vl_g = g_vTl + (size_t)bh * ND * NT;

    const uint32_t sQh = sb, sQl = sb + 16384;

    auto load_kv = [&](int jt, int st) {
        const int k0 = jt * 64;
        const uint32_t base = sb + 32768 + st * 32768;
#pragma unroll
        for (int u = 0; u < 2; u++) {
            const int idx = tid + u * 256;            // 0..511
            const int r = idx >> 3, c = (idx & 7) * 16;
            const uint32_t sw = SW128(r * 128 + c);
            CP_ASYNC16(base +         sw, (const char*)(Kh_g + (size_t)(k0 + r) * ND) + c);
            CP_ASYNC16(base +  8192 + sw, (const char*)(Kl_g + (size_t)(k0 + r) * ND) + c);
            CP_ASYNC16(base + 16384 + sw, (const char*)(Vh_g + (size_t)r * NT + k0) + c);
            CP_ASYNC16(base + 24576 + sw, (const char*)(Vl_g + (size_t)r * NT + k0) + c);
        }
        CP_COMMIT();
    };

    // Q tile load (with group 0)
#pragma unroll
    for (int u = 0; u < 4; u++) {
        const int idx = tid + u * 256;                // 0..1023
        const int r = idx >> 3, c = (idx & 7) * 16;
        const uint32_t sw = SW128(r * 128 + c);
        CP_ASYNC16(sQh + sw, (const char*)(Qh_g + (size_t)r * ND) + c);
        CP_ASYNC16(sQl + sw, (const char*)(Ql_g + (size_t)r * ND) + c);
    }
    load_kv(0, 0);
    load_kv(1, 1);

    const int nkt = 2 * qt + 2;
    const uint32_t lrow = lane & 15, lcolB = (lane >> 4) * 16;

    uint32_t qfh[4][4], qfl[4][4];
    float m0 = -1e30f, m1 = -1e30f, l0 = 0.0f, l1 = 0.0f;
    float o[8][4];
#pragma unroll
    for (int j = 0; j < 8; j++)
#pragma unroll
        for (int f = 0; f < 4; f++) o[j][f] = 0.0f;

    for (int jt = 0; jt < nkt; jt++) {
        const int st = jt & 1;
        if (jt + 1 < nkt) CP_WAIT(1); else CP_WAIT(0);
        __syncthreads();

        if (jt == 0) {
#pragma unroll
            for (int kt = 0; kt < 4; kt++) {
                const uint32_t off = SW128((w * 16 + lrow) * 128 + kt * 32 + lcolB);
                ldm_x4(qfh[kt], sQh + off);
                ldm_x4(qfl[kt], sQl + off);
            }
        }

        const bool diag0 = (jt == 2 * qt);
        const bool diag1 = (jt == 2 * qt + 1);
        const bool skip  = diag1 && (w < 4);    // fully masked sub-tile

        if (!skip) {
            const uint32_t kb = sb + 32768 + st * 32768;

            // S = Q K^T (split-3)
            float s[8][4];
#pragma unroll
            for (int j = 0; j < 8; j++)
#pragma unroll
                for (int f = 0; f < 4; f++) s[j][f] = 0.0f;

#pragma unroll
            for (int kt = 0; kt < 4; kt++) {
                uint32_t bKh[4][4], bKl[4][4];
#pragma unroll
                for (int j2 = 0; j2 < 4; j2++) {
                    const uint32_t off = SW128((j2 * 16 + lrow) * 128 + kt * 32 + lcolB);
                    ldm_x4(bKh[j2], kb + off);
                    ldm_x4(bKl[j2], kb + 8192 + off);
                }
#pragma unroll
                for (int j = 0; j < 8; j++) {
                    const int j2 = j >> 1, od = j & 1;
                    mma_bf16(s[j], qfh[kt], bKh[j2][od], bKh[j2][od + 2]);
                    mma_bf16(s[j], qfh[kt], bKl[j2][od], bKl[j2][od + 2]);
                    mma_bf16(s[j], qfl[kt], bKh[j2][od], bKh[j2][od + 2]);
                }
            }

            // causal mask on diagonal sub-tiles
            if ((diag0 && w < 4) || diag1) {
                const int qloc  = w * 16 + (lane >> 2);
                const int kbase = diag1 ? 64 : 0;
#pragma unroll
                for (int j = 0; j < 8; j++) {
                    const int kc = kbase + j * 8 + (lane & 3) * 2;
                    if (kc     > qloc)     s[j][0] = -1e30f;
                    if (kc + 1 > qloc)     s[j][1] = -1e30f;
                    if (kc     > qloc + 8) s[j][2] = -1e30f;
                    if (kc + 1 > qloc + 8) s[j][3] = -1e30f;
                }
            }

            // online softmax (exp2 domain; rows r=lane>>2 and r+8)
            float mx0 = -1e30f, mx1 = -1e30f;
#pragma unroll
            for (int j = 0; j < 8; j++) {
                mx0 = fmaxf(mx0, fmaxf(s[j][0], s[j][1]));
                mx1 = fmaxf(mx1, fmaxf(s[j][2], s[j][3]));
            }
            mx0 = fmaxf(mx0, __shfl_xor_sync(0xffffffffu, mx0, 1));
            mx0 = fmaxf(mx0, __shfl_xor_sync(0xffffffffu, mx0, 2));
            mx1 = fmaxf(mx1, __shfl_xor_sync(0xffffffffu, mx1, 1));
            mx1 = fmaxf(mx1, __shfl_xor_sync(0xffffffffu, mx1, 2));
            const float mn0 = fmaxf(m0, mx0), mn1 = fmaxf(m1, mx1);
            const float f0 = exp2f(m0 - mn0), f1 = exp2f(m1 - mn1);
            float rs0 = 0.0f, rs1 = 0.0f;
#pragma unroll
            for (int j = 0; j < 8; j++) {
                s[j][0] = exp2f(s[j][0] - mn0);
                s[j][1] = exp2f(s[j][1] - mn0);
                s[j][2] = exp2f(s[j][2] - mn1);
                s[j][3] = exp2f(s[j][3] - mn1);
                rs0 += s[j][0] + s[j][1];
                rs1 += s[j][2] + s[j][3];
            }
            rs0 += __shfl_xor_sync(0xffffffffu, rs0, 1);
            rs0 += __shfl_xor_sync(0xffffffffu, rs0, 2);
            rs1 += __shfl_xor_sync(0xffffffffu, rs1, 1);
            rs1 += __shfl_xor_sync(0xffffffffu, rs1, 2);
            l0 = l0 * f0 + rs0; m0 = mn0;
            l1 = l1 * f1 + rs1; m1 = mn1;
#pragma unroll
            for (int j = 0; j < 8; j++) {
                o[j][0] *= f0; o[j][1] *= f0;
                o[j][2] *= f1; o[j][3] *= f1;
            }

            // repack P (C-frag -> A-frag), split hi/lo
            uint32_t ph[4][4], pl[4][4];
#pragma unroll
            for (int kt = 0; kt < 4; kt++) {
                pack_split(s[2 * kt][0],     s[2 * kt][1],     ph[kt][0], pl[kt][0]);
                pack_split(s[2 * kt][2],     s[2 * kt][3],     ph[kt][1], pl[kt][1]);
                pack_split(s[2 * kt + 1][0], s[2 * kt + 1][1], ph[kt][2], pl[kt][2]);
                pack_split(s[2 * kt + 1][2], s[2 * kt + 1][3], ph[kt][3], pl[kt][3]);
            }

            // O += P V (split-3), B = V^T smem [d][key]
            const uint32_t vb = kb + 16384;
#pragma unroll
            for (int kt = 0; kt < 4; kt++) {
                uint32_t bVh[4][4], bVl[4][4];
#pragma unroll
                for (int j2 = 0; j2 < 4; j2++) {
                    const uint32_t off = SW128((j2 * 16 + lrow) * 128 + kt * 32 + lcolB);
                    ldm_x4(bVh[j2], vb + off);
                    ldm_x4(bVl[j2], vb + 8192 + off);
                }
#pragma unroll
                for (int j = 0; j < 8; j++) {
                    const int j2 = j >> 1, od = j & 1;
                    mma_bf16(o[j], ph[kt], bVh[j2][od], bVh[j2][od + 2]);
                    mma_bf16(o[j], ph[kt], bVl[j2][od], bVl[j2][od + 2]);
                    mma_bf16(o[j], pl[kt], bVh[j2][od], bVh[j2][od + 2]);
                }
            }
        }

        __syncthreads();
        if (jt + 2 < nkt) load_kv(jt + 2, st);
    }

    // Epilogue: normalize, split, write g_atth/g_attl [B,T,C]
    const int b = bh >> 4, h = bh & 15;
    const int r0g = q0 + w * 16 + (lane >> 2);
    const float inv0 = 1.0f / l0, inv1 = 1.0f / l1;
#pragma unroll
    for (int j = 0; j < 8; j++) {
        const int dc = j * 8 + (lane & 3) * 2;
        const size_t base = ((size_t)(b * NT + r0g)) * NC + h * 64 + dc;
        uint32_t hi, lo;
        pack_split(o[j][0] * inv0, o[j][1] * inv0, hi, lo);
        *(uint32_t*)&g_atth[base] = hi;
        *(uint32_t*)&g_attl[base] = lo;
        pack_split(o[j][2] * inv1, o[j][3] * inv1, hi, lo);
        *(uint32_t*)&g_atth[base + 8 * NC] = hi;
        *(uint32_t*)&g_attl[base + 8 * NC] = lo;
    }
}

// ---------------------------------------------------------------------------
// kernel_launch
// ---------------------------------------------------------------------------
extern "C" void kernel_launch(void* const* d_in, const int* in_sizes, int n_in,
                              void* d_out, int out_size)
{
    const float* x     = (const float*)d_in[0];
    const float* w_qkv = (const float*)d_in[1];
    const float* b_qkv = (const float*)d_in[2];
    const float* w_out = (const float*)d_in[3];
    const float* b_out = (const float*)d_in[4];
    float* out = (float*)d_out;

    cudaFuncSetAttribute((const void*)flash2_kernel,
                         cudaFuncAttributeMaxDynamicSharedMemorySize, FL2_SMEM);
    cudaFuncSetAttribute((const void*)gemm_mma<NQKV, 1>,
                         cudaFuncAttributeMaxDynamicSharedMemorySize, GEMM_SMEM);
    cudaFuncSetAttribute((const void*)gemm_mma<NC, 0>,
                         cudaFuncAttributeMaxDynamicSharedMemorySize, GEMM_SMEM);

    void *p_ah, *p_al, *p_wqh, *p_wql, *p_woh, *p_wol, *p_atth, *p_attl;
    cudaGetSymbolAddress(&p_ah,   g_ah);
    cudaGetSymbolAddress(&p_al,   g_al);
    cudaGetSymbolAddress(&p_wqh,  g_wqT_h);
    cudaGetSymbolAddress(&p_wql,  g_wqT_l);
    cudaGetSymbolAddress(&p_woh,  g_woT_h);
    cudaGetSymbolAddress(&p_wol,  g_woT_l);
    cudaGetSymbolAddress(&p_atth, g_atth);
    cudaGetSymbolAddress(&p_attl, g_attl);

    const int n4 = NM * NC / 4;

    // 1) Split x, transpose+split weights
    convert_split_kernel<<<(n4 + 255) / 256, 256>>>(
        x, (__nv_bfloat16*)p_ah, (__nv_bfloat16*)p_al, n4);
    transpose_split_kernel<<<dim3(NQKV / 32, NC / 32), dim3(32, 8)>>>(
        w_qkv, (__nv_bfloat16*)p_wqh, (__nv_bfloat16*)p_wql, NC, NQKV);
    transpose_split_kernel<<<dim3(NC / 32, NC / 32), dim3(32, 8)>>>(
        w_out, (__nv_bfloat16*)p_woh, (__nv_bfloat16*)p_wol, NC, NC);

    // 2) QKV projection -> pre-split bf16 flash operands
    gemm_mma<NQKV, 1><<<dim3(NQKV / 128, NM / 128), 256, GEMM_SMEM>>>(
        (const __nv_bfloat16*)p_ah, (const __nv_bfloat16*)p_al,
        (const __nv_bfloat16*)p_wqh, (const __nv_bfloat16*)p_wql,
        b_qkv, nullptr);

    // 3) Tensor-core causal flash attention -> g_atth/g_attl
    flash2_kernel<<<dim3(NT / 128, NB * NH), 256, FL2_SMEM>>>();

    // 4) Output projection
    gemm_mma<NC, 0><<<dim3(NC / 128, NM / 128), 256, GEMM_SMEM>>>(
        (const __nv_bfloat16*)p_atth, (const __nv_bfloat16*)p_attl,
        (const __nv_bfloat16*)p_woh, (const __nv_bfloat16*)p_wol,
        b_out, out);
}